// round 15
// baseline (speedup 1.0000x reference)
#include <cuda_runtime.h>
#include <cuda_fp16.h>
#include <math.h>
#include <stdint.h>

// ---------------- problem constants ----------------
#define NN      100000
#define NE      800000
#define DD      64
#define RM      8
#define NM      5000
#define NRE     40000
#define RR      4
#define NB      1024
#define DH      512
#define DO      703

// ---------------- scratch ----------------
__device__ __half g_hW [(size_t)RM * NN * DD];   // 102.4 MB fp16
__device__ __half g_h1 [(size_t)NN * DD];        // fp16
__device__ __half g_Wh [(2 * RM + RR) * 64 * 64];
__device__ float g_atts[(size_t)RM * NN];
__device__ float g_attd[(size_t)RM * NN];
__device__ int   g_deg   [NN];
__device__ int   g_rowptr[NN + 1];
__device__ int   g_cursor[NN];
__device__ int   g_bsum[128];
__device__ int   g_boff[130];
__device__ uint32_t g_epk[NE];
__device__ int   g_deg2   [NM];
__device__ int   g_rowptr2[NM + 1];
__device__ int   g_cursor2[NM];
__device__ int   g_bsum2[8];
__device__ int   g_boff2[10];
__device__ uint32_t g_epk2[NRE];
__device__ float g_mol [(size_t)NM * DD];
__device__ float g_feat[(size_t)NB * 2 * DD];
__device__ float g_hid [(size_t)NB * DH];

__device__ __forceinline__ void red_add_v4(float* p, float4 v) {
    asm volatile("red.global.add.v4.f32 [%0], {%1,%2,%3,%4};"
                 :: "l"(p), "f"(v.x), "f"(v.y), "f"(v.z), "f"(v.w) : "memory");
}
__device__ __forceinline__ void red_add_v2(float* p, float2 v) {
    asm volatile("red.global.add.v2.f32 [%0], {%1,%2};"
                 :: "l"(p), "f"(v.x), "f"(v.y) : "memory");
}

__global__ void filli_kernel(int* __restrict__ p, int v, int n) {
    int i = blockIdx.x * blockDim.x + threadIdx.x;
    if (i < n) p[i] = v;
}

__global__ void prep_wh_kernel(const float* __restrict__ W1, const float* __restrict__ W2,
                               const float* __restrict__ Wr, __half* __restrict__ Wh)
{
    int i = blockIdx.x * blockDim.x + threadIdx.x;
    const int n1 = RM * 4096, n2 = 2 * RM * 4096, n3 = (2 * RM + RR) * 4096;
    float v;
    if (i < n1)       v = W1[i];
    else if (i < n2)  v = W2[i - n1];
    else if (i < n3)  v = Wr[i - n2];
    else return;
    Wh[i] = __float2half(v);
}

#define Z_MOL4   (NM * 16)
#define Z_FEAT4  (NB * 32)
__global__ void fill_all_kernel(float4* __restrict__ mol, float4* __restrict__ feat)
{
    int i = blockIdx.x * blockDim.x + threadIdx.x;
    float4 z = make_float4(0.f, 0.f, 0.f, 0.f);
    if (i < Z_MOL4) mol[i] = z;
    if (i < Z_FEAT4) feat[i] = z;
}

// ================= CSR build (shared by atom + reaction graphs) =================
__global__ void hist_kernel(const int* __restrict__ dst, int* __restrict__ deg, int E) {
    int e = blockIdx.x * blockDim.x + threadIdx.x;
    if (e < E) atomicAdd(&deg[dst[e]], 1);
}

__global__ void scan_bsum_kernel(const int* __restrict__ deg, int* __restrict__ bsum, int N) {
    int b = blockIdx.x, t = threadIdx.x;
    int base = b * 1024 + t;
    int s = 0;
    #pragma unroll
    for (int q = 0; q < 4; q++) { int i = base + q * 256; if (i < N) s += deg[i]; }
    #pragma unroll
    for (int o = 16; o; o >>= 1) s += __shfl_xor_sync(0xffffffffu, s, o);
    __shared__ int ws[8];
    if ((t & 31) == 0) ws[t >> 5] = s;
    __syncthreads();
    if (t == 0) { int tot = 0; for (int i = 0; i < 8; i++) tot += ws[i]; bsum[b] = tot; }
}

__global__ void scan_sums_kernel(const int* __restrict__ bsum, int* __restrict__ boff, int nb) {
    int t = threadIdx.x, lane = t & 31, w = t >> 5;
    int v = (t < nb) ? bsum[t] : 0;
    int inc = v;
    #pragma unroll
    for (int o = 1; o < 32; o <<= 1) {
        int nv = __shfl_up_sync(0xffffffffu, inc, o);
        if (lane >= o) inc += nv;
    }
    __shared__ int ws[4];
    if (lane == 31) ws[w] = inc;
    __syncthreads();
    int add = 0;
    for (int i = 0; i < w; i++) add += ws[i];
    if (t < nb) boff[t] = add + inc - v;
    if (t == 0) boff[nb] = ws[0] + ws[1] + ws[2] + ws[3];
}

__global__ void scan_final_kernel(const int* __restrict__ deg, const int* __restrict__ boff,
                                  int* __restrict__ rowptr, int* __restrict__ cursor, int N, int nb) {
    int b = blockIdx.x, t = threadIdx.x, lane = t & 31, wid = t >> 5;
    int idx0 = b * 1024 + t * 4;
    int v0 = 0, v1 = 0, v2 = 0, v3 = 0;
    if (idx0 + 0 < N) v0 = deg[idx0 + 0];
    if (idx0 + 1 < N) v1 = deg[idx0 + 1];
    if (idx0 + 2 < N) v2 = deg[idx0 + 2];
    if (idx0 + 3 < N) v3 = deg[idx0 + 3];
    int tot = v0 + v1 + v2 + v3;
    int inc = tot;
    #pragma unroll
    for (int o = 1; o < 32; o <<= 1) {
        int nv = __shfl_up_sync(0xffffffffu, inc, o);
        if (lane >= o) inc += nv;
    }
    __shared__ int wsum[8], woff[8];
    if (lane == 31) wsum[wid] = inc;
    __syncthreads();
    if (t == 0) { int a = 0; for (int i = 0; i < 8; i++) { woff[i] = a; a += wsum[i]; } }
    __syncthreads();
    int run = boff[b] + woff[wid] + inc - tot;
    if (idx0 + 0 < N) { rowptr[idx0 + 0] = run; cursor[idx0 + 0] = run; } run += v0;
    if (idx0 + 1 < N) { rowptr[idx0 + 1] = run; cursor[idx0 + 1] = run; } run += v1;
    if (idx0 + 2 < N) { rowptr[idx0 + 2] = run; cursor[idx0 + 2] = run; } run += v2;
    if (idx0 + 3 < N) { rowptr[idx0 + 3] = run; cursor[idx0 + 3] = run; }
    if (b == 0 && t == 0) rowptr[N] = boff[nb];
}

__global__ void scatter_kernel(const int* __restrict__ src, const int* __restrict__ dst,
                               const int* __restrict__ rel,
                               int* __restrict__ cursor, uint32_t* __restrict__ epk, int E) {
    int e = blockIdx.x * blockDim.x + threadIdx.x;
    if (e >= E) return;
    int pos = atomicAdd(&cursor[dst[e]], 1);
    epk[pos] = (uint32_t)src[e] | ((uint32_t)rel[e] << 20);
}

// ================= warp-MMA helpers =================
__device__ __forceinline__ uint32_t smem_u32(const void* p) {
    return (uint32_t)__cvta_generic_to_shared(p);
}
#define LDSM_X4(r0, r1, r2, r3, addr) \
    asm volatile("ldmatrix.sync.aligned.m8n8.x4.shared.b16 {%0,%1,%2,%3}, [%4];" \
                 : "=r"(r0), "=r"(r1), "=r"(r2), "=r"(r3) : "r"(addr))
#define LDSM_X2T(r0, r1, addr) \
    asm volatile("ldmatrix.sync.aligned.m8n8.x2.trans.shared.b16 {%0,%1}, [%2];" \
                 : "=r"(r0), "=r"(r1) : "r"(addr))
#define MMA16816(c, a, b) \
    asm volatile("mma.sync.aligned.m16n8k16.row.col.f32.f16.f16.f32 " \
                 "{%0,%1,%2,%3}, {%4,%5,%6,%7}, {%8,%9}, {%0,%1,%2,%3};" \
                 : "+f"((c)[0]), "+f"((c)[1]), "+f"((c)[2]), "+f"((c)[3]) \
                 : "r"((a)[0]), "r"((a)[1]), "r"((a)[2]), "r"((a)[3]), \
                   "r"((b)[0]), "r"((b)[1]))
#define CP_ASYNC16(dst, src) \
    asm volatile("cp.async.ca.shared.global [%0], [%1], 16;" :: "r"(dst), "l"(src) : "memory")
#define CP_COMMIT()  asm volatile("cp.async.commit_group;" ::: "memory")
#define CP_WAIT0()   asm volatile("cp.async.wait_group 0;" ::: "memory")

// ---------------- hW GEMM on HMMA + fused attention-logit epilogue ----------------
template<typename TIN>
__global__ __launch_bounds__(128)
void hw_mma_kernel(const TIN* __restrict__ h,
                   const __half* __restrict__ Wh,
                   const float* __restrict__ a_src,
                   const float* __restrict__ a_dst,
                   __half* __restrict__ hW,
                   float* __restrict__ att_s,
                   float* __restrict__ att_d,
                   int N, int R)
{
    __shared__ __align__(16) __half sa [128 * 72];
    __shared__ __align__(16) __half swt[2][64 * 72];
    __shared__ float sas[8 * 64], sad[8 * 64];

    const int tid  = threadIdx.x;
    const int wid  = tid >> 5;
    const int lane = tid & 31;
    const int n0   = blockIdx.x * 128;

    {
        #pragma unroll
        for (int it = 0; it < 4; it++) {
            int chunk = it * 128 + tid;
            int k = chunk >> 3, c8 = (chunk & 7) * 8;
            CP_ASYNC16(smem_u32(&swt[0][k * 72 + c8]), Wh + k * 64 + c8);
        }
        CP_COMMIT();
    }

    for (int i = tid; i < R * 64; i += 128) { sas[i] = a_src[i]; sad[i] = a_dst[i]; }

    #pragma unroll
    for (int it = 0; it < 8; it++) {
        int chunk = it * 128 + tid;
        int row = chunk >> 3;
        int c8  = (chunk & 7) * 8;
        int n = n0 + row;
        if (sizeof(TIN) == 4) {
            float4 a = make_float4(0.f,0.f,0.f,0.f), b = a;
            if (n < N) {
                a = *(const float4*)((const float*)h + (size_t)n * 64 + c8);
                b = *(const float4*)((const float*)h + (size_t)n * 64 + c8 + 4);
            }
            __half2 pk[4];
            pk[0] = __floats2half2_rn(a.x, a.y);
            pk[1] = __floats2half2_rn(a.z, a.w);
            pk[2] = __floats2half2_rn(b.x, b.y);
            pk[3] = __floats2half2_rn(b.z, b.w);
            *(uint4*)&sa[row * 72 + c8] = *(uint4*)pk;
        } else {
            uint4 v = make_uint4(0u, 0u, 0u, 0u);
            if (n < N) v = *(const uint4*)((const __half*)h + (size_t)n * 64 + c8);
            *(uint4*)&sa[row * 72 + c8] = v;
        }
    }
    CP_WAIT0();
    __syncthreads();

    uint32_t afrag[2][4][4];
    {
        const int l15 = lane & 15;
        const int lhi = lane >> 4;
        #pragma unroll
        for (int mt = 0; mt < 2; mt++)
            #pragma unroll
            for (int kk = 0; kk < 4; kk++) {
                uint32_t addr = smem_u32(&sa[(wid * 32 + mt * 16 + l15) * 72 + kk * 16 + lhi * 8]);
                LDSM_X4(afrag[mt][kk][0], afrag[mt][kk][1],
                        afrag[mt][kk][2], afrag[mt][kk][3], addr);
            }
    }

    const int t4 = lane >> 2;
    const int t2 = (lane & 3) * 2;

    for (int r = 0; r < R; r++) {
        const int buf = r & 1;

        float c[2][8][4];
        #pragma unroll
        for (int mt = 0; mt < 2; mt++)
            #pragma unroll
            for (int j = 0; j < 8; j++)
                #pragma unroll
                for (int q = 0; q < 4; q++) c[mt][j][q] = 0.f;

        #pragma unroll
        for (int kk = 0; kk < 4; kk++) {
            uint32_t b[8][2];
            const int l15 = lane & 15;
            #pragma unroll
            for (int j = 0; j < 8; j++) {
                uint32_t addr = smem_u32(&swt[buf][(kk * 16 + l15) * 72 + j * 8]);
                LDSM_X2T(b[j][0], b[j][1], addr);
            }
            #pragma unroll
            for (int mt = 0; mt < 2; mt++)
                #pragma unroll
                for (int j = 0; j < 8; j++)
                    MMA16816(c[mt][j], afrag[mt][kk], b[j]);
        }

        if (r + 1 < R) {
            const __half* Wn = Wh + (size_t)(r + 1) * 4096;
            #pragma unroll
            for (int it = 0; it < 4; it++) {
                int chunk = it * 128 + tid;
                int k = chunk >> 3, c8 = (chunk & 7) * 8;
                CP_ASYNC16(smem_u32(&swt[1 - buf][k * 72 + c8]), Wn + k * 64 + c8);
            }
            CP_COMMIT();
        }

        #pragma unroll
        for (int mt = 0; mt < 2; mt++) {
            float ps0 = 0.f, pd0 = 0.f, ps1 = 0.f, pd1 = 0.f;
            #pragma unroll
            for (int j = 0; j < 8; j++) {
                float as0 = sas[r * 64 + j * 8 + t2], as1 = sas[r * 64 + j * 8 + t2 + 1];
                float ad0 = sad[r * 64 + j * 8 + t2], ad1 = sad[r * 64 + j * 8 + t2 + 1];
                ps0 += c[mt][j][0] * as0 + c[mt][j][1] * as1;
                pd0 += c[mt][j][0] * ad0 + c[mt][j][1] * ad1;
                ps1 += c[mt][j][2] * as0 + c[mt][j][3] * as1;
                pd1 += c[mt][j][2] * ad0 + c[mt][j][3] * ad1;
            }
            #pragma unroll
            for (int o = 1; o <= 2; o <<= 1) {
                ps0 += __shfl_xor_sync(0xffffffffu, ps0, o);
                pd0 += __shfl_xor_sync(0xffffffffu, pd0, o);
                ps1 += __shfl_xor_sync(0xffffffffu, ps1, o);
                pd1 += __shfl_xor_sync(0xffffffffu, pd1, o);
            }
            if ((lane & 3) == 0) {
                int n1 = n0 + wid * 32 + mt * 16 + t4;
                int n2 = n1 + 8;
                if (n1 < N) { att_s[(size_t)r * N + n1] = ps0; att_d[(size_t)r * N + n1] = pd0; }
                if (n2 < N) { att_s[(size_t)r * N + n2] = ps1; att_d[(size_t)r * N + n2] = pd1; }
            }
        }

        #pragma unroll
        for (int mt = 0; mt < 2; mt++) {
            int rr = wid * 32 + mt * 16 + t4;
            #pragma unroll
            for (int j = 0; j < 8; j++) {
                *(__half2*)&sa[rr * 72 + j * 8 + t2]       = __floats2half2_rn(c[mt][j][0], c[mt][j][1]);
                *(__half2*)&sa[(rr + 8) * 72 + j * 8 + t2] = __floats2half2_rn(c[mt][j][2], c[mt][j][3]);
            }
        }
        __syncwarp();
        #pragma unroll
        for (int it = 0; it < 8; it++) {
            int idx = it * 32 + lane;
            int rowl = idx >> 3;
            int q    = idx & 7;
            int row  = wid * 32 + rowl;
            int n = n0 + row;
            if (n < N)
                *(uint4*)&hW[((size_t)r * N + n) * 64 + q * 8] = *(uint4*)&sa[row * 72 + q * 8];
        }
        CP_WAIT0();
        __syncthreads();
    }
}

// ---------------- CSR edge aggregation (atom + reaction) ----------------
// SEG=false: fp16 rows to outh. SEG=true: red-add fp32 into outh[seg[w]*ostride+ooff].
template<bool SEG>
__global__ void edge_agg_kernel(const int* __restrict__ rowptr, const uint32_t* __restrict__ epk,
                                const float* __restrict__ att_s, const float* __restrict__ att_d,
                                const __half* __restrict__ hW, const int* __restrict__ seg,
                                void* __restrict__ outh, int N, int R, int ostride, int ooff)
{
    int w = (blockIdx.x * blockDim.x + threadIdx.x) >> 5;
    int lane = threadIdx.x & 31;
    if (w >= N) return;
    int beg = rowptr[w], end = rowptr[w + 1];
    float adv = (lane < R) ? att_d[(size_t)lane * N + w] : 0.f;
    float acc0 = 0.f, acc1 = 0.f, ssum = 0.f;
    int e = beg;
    for (; e + 3 < end; e += 4) {
        uint32_t p0 = epk[e], p1 = epk[e + 1], p2 = epk[e + 2], p3 = epk[e + 3];
        int s0 = p0 & 0xFFFFF, r0 = p0 >> 20;
        int s1 = p1 & 0xFFFFF, r1 = p1 >> 20;
        int s2 = p2 & 0xFFFFF, r2 = p2 >> 20;
        int s3 = p3 & 0xFFFFF, r3 = p3 >> 20;
        float sc0 = att_s[(size_t)r0 * N + s0] + __shfl_sync(0xffffffffu, adv, r0);
        float sc1 = att_s[(size_t)r1 * N + s1] + __shfl_sync(0xffffffffu, adv, r1);
        float sc2 = att_s[(size_t)r2 * N + s2] + __shfl_sync(0xffffffffu, adv, r2);
        float sc3 = att_s[(size_t)r3 * N + s3] + __shfl_sync(0xffffffffu, adv, r3);
        sc0 = (sc0 > 0.f) ? sc0 : 0.2f * sc0;
        sc1 = (sc1 > 0.f) ? sc1 : 0.2f * sc1;
        sc2 = (sc2 > 0.f) ? sc2 : 0.2f * sc2;
        sc3 = (sc3 > 0.f) ? sc3 : 0.2f * sc3;
        float x0 = __expf(sc0), x1 = __expf(sc1), x2 = __expf(sc2), x3 = __expf(sc3);
        __half2 h0 = *(const __half2*)&hW[((size_t)r0 * N + s0) * 64 + lane * 2];
        __half2 h1 = *(const __half2*)&hW[((size_t)r1 * N + s1) * 64 + lane * 2];
        __half2 h2 = *(const __half2*)&hW[((size_t)r2 * N + s2) * 64 + lane * 2];
        __half2 h3 = *(const __half2*)&hW[((size_t)r3 * N + s3) * 64 + lane * 2];
        float2 f0 = __half22float2(h0), f1 = __half22float2(h1);
        float2 f2 = __half22float2(h2), f3 = __half22float2(h3);
        acc0 = fmaf(x0, f0.x, acc0); acc1 = fmaf(x0, f0.y, acc1);
        acc0 = fmaf(x1, f1.x, acc0); acc1 = fmaf(x1, f1.y, acc1);
        acc0 = fmaf(x2, f2.x, acc0); acc1 = fmaf(x2, f2.y, acc1);
        acc0 = fmaf(x3, f3.x, acc0); acc1 = fmaf(x3, f3.y, acc1);
        ssum += (x0 + x1) + (x2 + x3);
    }
    for (; e < end; e++) {
        uint32_t p0 = epk[e];
        int s0 = p0 & 0xFFFFF, r0 = p0 >> 20;
        float sc0 = att_s[(size_t)r0 * N + s0] + __shfl_sync(0xffffffffu, adv, r0);
        sc0 = (sc0 > 0.f) ? sc0 : 0.2f * sc0;
        float x0 = __expf(sc0);
        __half2 h0 = *(const __half2*)&hW[((size_t)r0 * N + s0) * 64 + lane * 2];
        float2 f0 = __half22float2(h0);
        acc0 = fmaf(x0, f0.x, acc0); acc1 = fmaf(x0, f0.y, acc1);
        ssum += x0;
    }
    float inv = 1.f / (ssum + 1e-9f);
    float v0 = acc0 * inv, v1 = acc1 * inv;
    v0 = (v0 > 0.f) ? v0 : expm1f(v0);
    v1 = (v1 > 0.f) ? v1 : expm1f(v1);
    if (SEG) {
        red_add_v2((float*)outh + (size_t)seg[w] * ostride + ooff + lane * 2, make_float2(v0, v1));
    } else {
        *(__half2*)((__half*)outh + (size_t)w * 64 + lane * 2) = __floats2half2_rn(v0, v1);
    }
}

__global__ void segsum_kernel(const float* __restrict__ x, const int* __restrict__ seg,
                              float* __restrict__ out, int n, int ostride, int ooff)
{
    int t = blockIdx.x * blockDim.x + threadIdx.x;
    int i = t >> 4;
    if (i >= n) return;
    int g = (t & 15) * 4;
    int s = seg[i];
    float4 v = *(const float4*)&x[(size_t)i * 64 + g];
    red_add_v4(&out[(size_t)s * ostride + ooff + g], v);
}

// ---------------- MLP head (32 rows/block) ----------------
__global__ void fc1_kernel(const float* __restrict__ feat, const float* __restrict__ w,
                           const float* __restrict__ b, const float* __restrict__ prelu,
                           float* __restrict__ out)
{
    const int r0 = blockIdx.x * 32;
    const int c0 = blockIdx.y * 128;
    __shared__ float fs[32][128];
    #pragma unroll
    for (int it = 0; it < 8; it++) {
        int idx4 = it * 128 + threadIdx.x;       // 1024 float4
        int row = idx4 >> 5, col = (idx4 & 31) * 4;
        *(float4*)&fs[row][col] = *(const float4*)&feat[(size_t)(r0 + row) * 128 + col];
    }
    __syncthreads();
    const int col = c0 + threadIdx.x;
    float acc[32];
    #pragma unroll
    for (int j = 0; j < 32; j++) acc[j] = 0.f;
    #pragma unroll 4
    for (int k = 0; k < 128; k++) {
        float wv = w[k * 512 + col];
        #pragma unroll
        for (int j = 0; j < 32; j++) acc[j] += fs[j][k] * wv;
    }
    float bb = b[col], p = prelu[0];
    #pragma unroll
    for (int j = 0; j < 32; j++) {
        float v = acc[j] + bb;
        out[(size_t)(r0 + j) * 512 + col] = (v > 0.f) ? v : p * v;
    }
}

// fc2: 32 rows/block, 64 KB dynamic smem for the hid tile.
__global__ void fc2_kernel(const float* __restrict__ hid, const float* __restrict__ w,
                           const float* __restrict__ b, float* __restrict__ out)
{
    extern __shared__ float hs[];   // [32][512]
    const int r0 = blockIdx.x * 32;
    const int c0 = blockIdx.y * 128;
    #pragma unroll
    for (int it = 0; it < 32; it++) {
        int idx4 = it * 128 + threadIdx.x;       // 4096 float4
        int row = idx4 >> 7, col = (idx4 & 127) * 4;
        *(float4*)&hs[row * 512 + col] = *(const float4*)&hid[(size_t)(r0 + row) * 512 + col];
    }
    __syncthreads();
    const int col = c0 + threadIdx.x;
    if (col >= DO) return;
    float acc[32];
    #pragma unroll
    for (int j = 0; j < 32; j++) acc[j] = 0.f;
    #pragma unroll 2
    for (int k = 0; k < 512; k++) {
        float wv = w[k * DO + col];
        #pragma unroll
        for (int j = 0; j < 32; j++) acc[j] += hs[j * 512 + k] * wv;
    }
    float bb = b[col];
    #pragma unroll
    for (int j = 0; j < 32; j++)
        out[(size_t)(r0 + j) * DO + col] = acc[j] + bb;
}

// ---------------- launch ----------------
static inline int cdiv(int a, int b) { return (a + b - 1) / b; }

extern "C" void kernel_launch(void* const* d_in, const int* in_sizes, int n_in,
                              void* d_out, int out_size)
{
    const float* node_feats = (const float*)d_in[0];
    const int*   edge_src   = (const int*)  d_in[1];
    const int*   edge_dst   = (const int*)  d_in[2];
    const int*   edge_rel   = (const int*)  d_in[3];
    const int*   node2mol   = (const int*)  d_in[4];
    const int*   rxn_src    = (const int*)  d_in[5];
    const int*   rxn_dst    = (const int*)  d_in[6];
    const int*   rxn_rel    = (const int*)  d_in[7];
    const int*   mol2rxn    = (const int*)  d_in[8];
    const float* W1    = (const float*)d_in[9];
    const float* as1   = (const float*)d_in[10];
    const float* ad1   = (const float*)d_in[11];
    const float* W2    = (const float*)d_in[12];
    const float* as2   = (const float*)d_in[13];
    const float* ad2   = (const float*)d_in[14];
    const float* Wr    = (const float*)d_in[15];
    const float* asr   = (const float*)d_in[16];
    const float* adr   = (const float*)d_in[17];
    const float* w_fc1 = (const float*)d_in[18];
    const float* b_fc1 = (const float*)d_in[19];
    const float* prelu = (const float*)d_in[20];
    const float* w_fc2 = (const float*)d_in[21];
    const float* b_fc2 = (const float*)d_in[22];
    float* out = (float*)d_out;

    __half *p_hW, *p_h1, *p_Wh;
    float *p_atts, *p_attd, *p_mol, *p_feat, *p_hid;
    int *p_deg, *p_rowptr, *p_cursor, *p_bsum, *p_boff;
    int *p_deg2, *p_rowptr2, *p_cursor2, *p_bsum2, *p_boff2;
    uint32_t *p_epk, *p_epk2;
    cudaGetSymbolAddress((void**)&p_hW,     g_hW);
    cudaGetSymbolAddress((void**)&p_h1,     g_h1);
    cudaGetSymbolAddress((void**)&p_Wh,     g_Wh);
    cudaGetSymbolAddress((void**)&p_atts,   g_atts);
    cudaGetSymbolAddress((void**)&p_attd,   g_attd);
    cudaGetSymbolAddress((void**)&p_deg,    g_deg);
    cudaGetSymbolAddress((void**)&p_rowptr, g_rowptr);
    cudaGetSymbolAddress((void**)&p_cursor, g_cursor);
    cudaGetSymbolAddress((void**)&p_bsum,   g_bsum);
    cudaGetSymbolAddress((void**)&p_boff,   g_boff);
    cudaGetSymbolAddress((void**)&p_epk,    g_epk);
    cudaGetSymbolAddress((void**)&p_deg2,   g_deg2);
    cudaGetSymbolAddress((void**)&p_rowptr2,g_rowptr2);
    cudaGetSymbolAddress((void**)&p_cursor2,g_cursor2);
    cudaGetSymbolAddress((void**)&p_bsum2,  g_bsum2);
    cudaGetSymbolAddress((void**)&p_boff2,  g_boff2);
    cudaGetSymbolAddress((void**)&p_epk2,   g_epk2);
    cudaGetSymbolAddress((void**)&p_mol,    g_mol);
    cudaGetSymbolAddress((void**)&p_feat,   g_feat);
    cudaGetSymbolAddress((void**)&p_hid,    g_hid);

    const int TB = 256;
    const int NBLK  = cdiv(NN, 1024);   // 98
    const int NBLK2 = cdiv(NM, 1024);   // 5
    const int WH_N = (2 * RM + RR) * 4096;

    cudaFuncSetAttribute(fc2_kernel, cudaFuncAttributeMaxDynamicSharedMemorySize, 32 * 512 * 4);

    // ===== pre-convert weights (main stream, needed by GEMM L1) =====
    prep_wh_kernel<<<cdiv(WH_N, TB), TB>>>(W1, W2, Wr, p_Wh);

    // ===== fork side stream =====
    cudaStream_t s2;
    cudaStreamCreateWithFlags(&s2, cudaStreamNonBlocking);
    cudaEvent_t ev_fork, ev_join, ev_join2, ev_mol, ev_seg;
    cudaEventCreateWithFlags(&ev_fork,  cudaEventDisableTiming);
    cudaEventCreateWithFlags(&ev_join,  cudaEventDisableTiming);
    cudaEventCreateWithFlags(&ev_join2, cudaEventDisableTiming);
    cudaEventCreateWithFlags(&ev_mol,   cudaEventDisableTiming);
    cudaEventCreateWithFlags(&ev_seg,   cudaEventDisableTiming);

    cudaEventRecord(ev_fork, 0);
    cudaStreamWaitEvent(s2, ev_fork, 0);

    // --- side: atom CSR + fills ---
    filli_kernel<<<cdiv(NN, TB), TB, 0, s2>>>(p_deg, 0, NN);
    hist_kernel<<<cdiv(NE, TB), TB, 0, s2>>>(edge_dst, p_deg, NE);
    scan_bsum_kernel<<<NBLK, 256, 0, s2>>>(p_deg, p_bsum, NN);
    scan_sums_kernel<<<1, 128, 0, s2>>>(p_bsum, p_boff, NBLK);
    scan_final_kernel<<<NBLK, 256, 0, s2>>>(p_deg, p_boff, p_rowptr, p_cursor, NN, NBLK);
    scatter_kernel<<<cdiv(NE, TB), TB, 0, s2>>>(edge_src, edge_dst, edge_rel, p_cursor, p_epk, NE);
    fill_all_kernel<<<cdiv(NB * 32 > NM * 16 ? NB * 32 : NM * 16, TB), TB, 0, s2>>>(
        (float4*)p_mol, (float4*)p_feat);
    cudaEventRecord(ev_join, s2);

    // --- side (continues): reaction CSR, hidden under atom layers ---
    filli_kernel<<<cdiv(NM, TB), TB, 0, s2>>>(p_deg2, 0, NM);
    hist_kernel<<<cdiv(NRE, TB), TB, 0, s2>>>(rxn_dst, p_deg2, NRE);
    scan_bsum_kernel<<<NBLK2, 256, 0, s2>>>(p_deg2, p_bsum2, NM);
    scan_sums_kernel<<<1, 128, 0, s2>>>(p_bsum2, p_boff2, NBLK2);
    scan_final_kernel<<<NBLK2, 256, 0, s2>>>(p_deg2, p_boff2, p_rowptr2, p_cursor2, NM, NBLK2);
    scatter_kernel<<<cdiv(NRE, TB), TB, 0, s2>>>(rxn_src, rxn_dst, rxn_rel, p_cursor2, p_epk2, NRE);
    cudaEventRecord(ev_join2, s2);

    // --- main: atom layer 1 ---
    hw_mma_kernel<float><<<cdiv(NN, 128), 128>>>(node_feats, p_Wh, as1, ad1,
                                                 p_hW, p_atts, p_attd, NN, RM);
    cudaStreamWaitEvent(0, ev_join, 0);
    edge_agg_kernel<false><<<cdiv(NN * 32, TB), TB>>>(p_rowptr, p_epk, p_atts, p_attd, p_hW,
                                                      (const int*)0, p_h1, NN, RM, 0, 0);

    // ===== atom layer 2 (reduces straight into mol) =====
    hw_mma_kernel<__half><<<cdiv(NN, 128), 128>>>(p_h1, p_Wh + (size_t)RM * 4096, as2, ad2,
                                                  p_hW, p_atts, p_attd, NN, RM);
    edge_agg_kernel<true><<<cdiv(NN * 32, TB), TB>>>(p_rowptr, p_epk, p_atts, p_attd, p_hW,
                                                     node2mol, p_mol, NN, RM, 64, 0);
    cudaEventRecord(ev_mol, 0);

    // --- side: direct mol sums into feat[:,64:] overlapping reaction GEMM ---
    cudaStreamWaitEvent(s2, ev_mol, 0);
    segsum_kernel<<<cdiv(NM * 16, TB), TB, 0, s2>>>(p_mol, mol2rxn, p_feat, NM, 128, 64);
    cudaEventRecord(ev_seg, s2);

    // ===== reaction-level RGAT (CSR path, straight into feat[:, :64]) =====
    hw_mma_kernel<float><<<cdiv(NM, 128), 128>>>(p_mol, p_Wh + (size_t)2 * RM * 4096, asr, adr,
                                                 p_hW, p_atts, p_attd, NM, RR);
    cudaStreamWaitEvent(0, ev_join2, 0);
    edge_agg_kernel<true><<<cdiv(NM * 32, TB), TB>>>(p_rowptr2, p_epk2, p_atts, p_attd, p_hW,
                                                     mol2rxn, p_feat, NM, RR, 128, 0);
    cudaStreamWaitEvent(0, ev_seg, 0);

    // ===== MLP head =====
    fc1_kernel<<<dim3(NB / 32, 4), 128>>>(p_feat, w_fc1, b_fc1, prelu, p_hid);
    fc2_kernel<<<dim3(NB / 32, 6), 128, 32 * 512 * 4>>>(p_hid, w_fc2, b_fc2, out);

    cudaEventDestroy(ev_fork);
    cudaEventDestroy(ev_join);
    cudaEventDestroy(ev_join2);
    cudaEventDestroy(ev_mol);
    cudaEventDestroy(ev_seg);
    cudaStreamDestroy(s2);
}

// round 16
// speedup vs baseline: 1.0375x; 1.0375x over previous
#include <cuda_runtime.h>
#include <cuda_fp16.h>
#include <math.h>
#include <stdint.h>

// ---------------- problem constants ----------------
#define NN      100000
#define NE      800000
#define DD      64
#define RM      8
#define NM      5000
#define NRE     40000
#define RR      4
#define NB      1024
#define DH      512
#define DO      703

// ---------------- scratch ----------------
__device__ __half g_hW [(size_t)RM * NN * DD];   // 102.4 MB fp16
__device__ __half g_h1 [(size_t)NN * DD];        // fp16
__device__ __half g_Wh [(2 * RM + RR) * 64 * 64];
__device__ float g_atts[(size_t)RM * NN];
__device__ float g_attd[(size_t)RM * NN];
__device__ int   g_deg   [NN];
__device__ int   g_rowptr[NN + 1];
__device__ int   g_cursor[NN];
__device__ int   g_bsum[128];
__device__ int   g_boff[130];
__device__ uint32_t g_epk[NE];
__device__ int   g_deg2   [NM];
__device__ int   g_rowptr2[NM + 1];
__device__ int   g_cursor2[NM];
__device__ int   g_bsum2[8];
__device__ int   g_boff2[10];
__device__ uint32_t g_epk2[NRE];
__device__ float g_mol [(size_t)NM * DD];
__device__ float g_feat[(size_t)NB * 2 * DD];
__device__ float g_hid [(size_t)NB * DH];

__device__ __forceinline__ void red_add_v4(float* p, float4 v) {
    asm volatile("red.global.add.v4.f32 [%0], {%1,%2,%3,%4};"
                 :: "l"(p), "f"(v.x), "f"(v.y), "f"(v.z), "f"(v.w) : "memory");
}
__device__ __forceinline__ void red_add_v2(float* p, float2 v) {
    asm volatile("red.global.add.v2.f32 [%0], {%1,%2};"
                 :: "l"(p), "f"(v.x), "f"(v.y) : "memory");
}

__global__ void filli_kernel(int* __restrict__ p, int v, int n) {
    int i = blockIdx.x * blockDim.x + threadIdx.x;
    if (i < n) p[i] = v;
}

__global__ void prep_wh_kernel(const float* __restrict__ W1, const float* __restrict__ W2,
                               const float* __restrict__ Wr, __half* __restrict__ Wh)
{
    int i = blockIdx.x * blockDim.x + threadIdx.x;
    const int n1 = RM * 4096, n2 = 2 * RM * 4096, n3 = (2 * RM + RR) * 4096;
    float v;
    if (i < n1)       v = W1[i];
    else if (i < n2)  v = W2[i - n1];
    else if (i < n3)  v = Wr[i - n2];
    else return;
    Wh[i] = __float2half(v);
}

#define Z_MOL4   (NM * 16)
#define Z_FEAT4  (NB * 32)
__global__ void fill_all_kernel(float4* __restrict__ mol, float4* __restrict__ feat)
{
    int i = blockIdx.x * blockDim.x + threadIdx.x;
    float4 z = make_float4(0.f, 0.f, 0.f, 0.f);
    if (i < Z_MOL4) mol[i] = z;
    if (i < Z_FEAT4) feat[i] = z;
}

// ================= CSR build =================
__global__ void hist_kernel(const int* __restrict__ dst, int* __restrict__ deg, int E) {
    int e = blockIdx.x * blockDim.x + threadIdx.x;
    if (e < E) atomicAdd(&deg[dst[e]], 1);
}

__global__ void scan_bsum_kernel(const int* __restrict__ deg, int* __restrict__ bsum, int N) {
    int b = blockIdx.x, t = threadIdx.x;
    int base = b * 1024 + t;
    int s = 0;
    #pragma unroll
    for (int q = 0; q < 4; q++) { int i = base + q * 256; if (i < N) s += deg[i]; }
    #pragma unroll
    for (int o = 16; o; o >>= 1) s += __shfl_xor_sync(0xffffffffu, s, o);
    __shared__ int ws[8];
    if ((t & 31) == 0) ws[t >> 5] = s;
    __syncthreads();
    if (t == 0) { int tot = 0; for (int i = 0; i < 8; i++) tot += ws[i]; bsum[b] = tot; }
}

__global__ void scan_sums_kernel(const int* __restrict__ bsum, int* __restrict__ boff, int nb) {
    int t = threadIdx.x, lane = t & 31, w = t >> 5;
    int v = (t < nb) ? bsum[t] : 0;
    int inc = v;
    #pragma unroll
    for (int o = 1; o < 32; o <<= 1) {
        int nv = __shfl_up_sync(0xffffffffu, inc, o);
        if (lane >= o) inc += nv;
    }
    __shared__ int ws[4];
    if (lane == 31) ws[w] = inc;
    __syncthreads();
    int add = 0;
    for (int i = 0; i < w; i++) add += ws[i];
    if (t < nb) boff[t] = add + inc - v;
    if (t == 0) boff[nb] = ws[0] + ws[1] + ws[2] + ws[3];
}

__global__ void scan_final_kernel(const int* __restrict__ deg, const int* __restrict__ boff,
                                  int* __restrict__ rowptr, int* __restrict__ cursor, int N, int nb) {
    int b = blockIdx.x, t = threadIdx.x, lane = t & 31, wid = t >> 5;
    int idx0 = b * 1024 + t * 4;
    int v0 = 0, v1 = 0, v2 = 0, v3 = 0;
    if (idx0 + 0 < N) v0 = deg[idx0 + 0];
    if (idx0 + 1 < N) v1 = deg[idx0 + 1];
    if (idx0 + 2 < N) v2 = deg[idx0 + 2];
    if (idx0 + 3 < N) v3 = deg[idx0 + 3];
    int tot = v0 + v1 + v2 + v3;
    int inc = tot;
    #pragma unroll
    for (int o = 1; o < 32; o <<= 1) {
        int nv = __shfl_up_sync(0xffffffffu, inc, o);
        if (lane >= o) inc += nv;
    }
    __shared__ int wsum[8], woff[8];
    if (lane == 31) wsum[wid] = inc;
    __syncthreads();
    if (t == 0) { int a = 0; for (int i = 0; i < 8; i++) { woff[i] = a; a += wsum[i]; } }
    __syncthreads();
    int run = boff[b] + woff[wid] + inc - tot;
    if (idx0 + 0 < N) { rowptr[idx0 + 0] = run; cursor[idx0 + 0] = run; } run += v0;
    if (idx0 + 1 < N) { rowptr[idx0 + 1] = run; cursor[idx0 + 1] = run; } run += v1;
    if (idx0 + 2 < N) { rowptr[idx0 + 2] = run; cursor[idx0 + 2] = run; } run += v2;
    if (idx0 + 3 < N) { rowptr[idx0 + 3] = run; cursor[idx0 + 3] = run; }
    if (b == 0 && t == 0) rowptr[N] = boff[nb];
}

__global__ void scatter_kernel(const int* __restrict__ src, const int* __restrict__ dst,
                               const int* __restrict__ rel,
                               int* __restrict__ cursor, uint32_t* __restrict__ epk, int E) {
    int e = blockIdx.x * blockDim.x + threadIdx.x;
    if (e >= E) return;
    int pos = atomicAdd(&cursor[dst[e]], 1);
    epk[pos] = (uint32_t)src[e] | ((uint32_t)rel[e] << 20);
}

// ================= warp-MMA helpers =================
__device__ __forceinline__ uint32_t smem_u32(const void* p) {
    return (uint32_t)__cvta_generic_to_shared(p);
}
#define LDSM_X4(r0, r1, r2, r3, addr) \
    asm volatile("ldmatrix.sync.aligned.m8n8.x4.shared.b16 {%0,%1,%2,%3}, [%4];" \
                 : "=r"(r0), "=r"(r1), "=r"(r2), "=r"(r3) : "r"(addr))
#define LDSM_X2T(r0, r1, addr) \
    asm volatile("ldmatrix.sync.aligned.m8n8.x2.trans.shared.b16 {%0,%1}, [%2];" \
                 : "=r"(r0), "=r"(r1) : "r"(addr))
#define MMA16816(c, a, b) \
    asm volatile("mma.sync.aligned.m16n8k16.row.col.f32.f16.f16.f32 " \
                 "{%0,%1,%2,%3}, {%4,%5,%6,%7}, {%8,%9}, {%0,%1,%2,%3};" \
                 : "+f"((c)[0]), "+f"((c)[1]), "+f"((c)[2]), "+f"((c)[3]) \
                 : "r"((a)[0]), "r"((a)[1]), "r"((a)[2]), "r"((a)[3]), \
                   "r"((b)[0]), "r"((b)[1]))
#define CP_ASYNC16(dst, src) \
    asm volatile("cp.async.ca.shared.global [%0], [%1], 16;" :: "r"(dst), "l"(src) : "memory")
#define CP_COMMIT()  asm volatile("cp.async.commit_group;" ::: "memory")
#define CP_WAIT0()   asm volatile("cp.async.wait_group 0;" ::: "memory")

// ---------------- hW GEMM on HMMA + fused attention-logit epilogue ----------------
template<typename TIN>
__global__ __launch_bounds__(128)
void hw_mma_kernel(const TIN* __restrict__ h,
                   const __half* __restrict__ Wh,
                   const float* __restrict__ a_src,
                   const float* __restrict__ a_dst,
                   __half* __restrict__ hW,
                   float* __restrict__ att_s,
                   float* __restrict__ att_d,
                   int N, int R)
{
    __shared__ __align__(16) __half sa [128 * 72];
    __shared__ __align__(16) __half swt[2][64 * 72];
    __shared__ float sas[8 * 64], sad[8 * 64];

    const int tid  = threadIdx.x;
    const int wid  = tid >> 5;
    const int lane = tid & 31;
    const int n0   = blockIdx.x * 128;

    {
        #pragma unroll
        for (int it = 0; it < 4; it++) {
            int chunk = it * 128 + tid;
            int k = chunk >> 3, c8 = (chunk & 7) * 8;
            CP_ASYNC16(smem_u32(&swt[0][k * 72 + c8]), Wh + k * 64 + c8);
        }
        CP_COMMIT();
    }

    for (int i = tid; i < R * 64; i += 128) { sas[i] = a_src[i]; sad[i] = a_dst[i]; }

    #pragma unroll
    for (int it = 0; it < 8; it++) {
        int chunk = it * 128 + tid;
        int row = chunk >> 3;
        int c8  = (chunk & 7) * 8;
        int n = n0 + row;
        if (sizeof(TIN) == 4) {
            float4 a = make_float4(0.f,0.f,0.f,0.f), b = a;
            if (n < N) {
                a = *(const float4*)((const float*)h + (size_t)n * 64 + c8);
                b = *(const float4*)((const float*)h + (size_t)n * 64 + c8 + 4);
            }
            __half2 pk[4];
            pk[0] = __floats2half2_rn(a.x, a.y);
            pk[1] = __floats2half2_rn(a.z, a.w);
            pk[2] = __floats2half2_rn(b.x, b.y);
            pk[3] = __floats2half2_rn(b.z, b.w);
            *(uint4*)&sa[row * 72 + c8] = *(uint4*)pk;
        } else {
            uint4 v = make_uint4(0u, 0u, 0u, 0u);
            if (n < N) v = *(const uint4*)((const __half*)h + (size_t)n * 64 + c8);
            *(uint4*)&sa[row * 72 + c8] = v;
        }
    }
    CP_WAIT0();
    __syncthreads();

    uint32_t afrag[2][4][4];
    {
        const int l15 = lane & 15;
        const int lhi = lane >> 4;
        #pragma unroll
        for (int mt = 0; mt < 2; mt++)
            #pragma unroll
            for (int kk = 0; kk < 4; kk++) {
                uint32_t addr = smem_u32(&sa[(wid * 32 + mt * 16 + l15) * 72 + kk * 16 + lhi * 8]);
                LDSM_X4(afrag[mt][kk][0], afrag[mt][kk][1],
                        afrag[mt][kk][2], afrag[mt][kk][3], addr);
            }
    }

    const int t4 = lane >> 2;
    const int t2 = (lane & 3) * 2;

    for (int r = 0; r < R; r++) {
        const int buf = r & 1;

        float c[2][8][4];
        #pragma unroll
        for (int mt = 0; mt < 2; mt++)
            #pragma unroll
            for (int j = 0; j < 8; j++)
                #pragma unroll
                for (int q = 0; q < 4; q++) c[mt][j][q] = 0.f;

        #pragma unroll
        for (int kk = 0; kk < 4; kk++) {
            uint32_t b[8][2];
            const int l15 = lane & 15;
            #pragma unroll
            for (int j = 0; j < 8; j++) {
                uint32_t addr = smem_u32(&swt[buf][(kk * 16 + l15) * 72 + j * 8]);
                LDSM_X2T(b[j][0], b[j][1], addr);
            }
            #pragma unroll
            for (int mt = 0; mt < 2; mt++)
                #pragma unroll
                for (int j = 0; j < 8; j++)
                    MMA16816(c[mt][j], afrag[mt][kk], b[j]);
        }

        if (r + 1 < R) {
            const __half* Wn = Wh + (size_t)(r + 1) * 4096;
            #pragma unroll
            for (int it = 0; it < 4; it++) {
                int chunk = it * 128 + tid;
                int k = chunk >> 3, c8 = (chunk & 7) * 8;
                CP_ASYNC16(smem_u32(&swt[1 - buf][k * 72 + c8]), Wn + k * 64 + c8);
            }
            CP_COMMIT();
        }

        #pragma unroll
        for (int mt = 0; mt < 2; mt++) {
            float ps0 = 0.f, pd0 = 0.f, ps1 = 0.f, pd1 = 0.f;
            #pragma unroll
            for (int j = 0; j < 8; j++) {
                float as0 = sas[r * 64 + j * 8 + t2], as1 = sas[r * 64 + j * 8 + t2 + 1];
                float ad0 = sad[r * 64 + j * 8 + t2], ad1 = sad[r * 64 + j * 8 + t2 + 1];
                ps0 += c[mt][j][0] * as0 + c[mt][j][1] * as1;
                pd0 += c[mt][j][0] * ad0 + c[mt][j][1] * ad1;
                ps1 += c[mt][j][2] * as0 + c[mt][j][3] * as1;
                pd1 += c[mt][j][2] * ad0 + c[mt][j][3] * ad1;
            }
            #pragma unroll
            for (int o = 1; o <= 2; o <<= 1) {
                ps0 += __shfl_xor_sync(0xffffffffu, ps0, o);
                pd0 += __shfl_xor_sync(0xffffffffu, pd0, o);
                ps1 += __shfl_xor_sync(0xffffffffu, ps1, o);
                pd1 += __shfl_xor_sync(0xffffffffu, pd1, o);
            }
            if ((lane & 3) == 0) {
                int n1 = n0 + wid * 32 + mt * 16 + t4;
                int n2 = n1 + 8;
                if (n1 < N) { att_s[(size_t)r * N + n1] = ps0; att_d[(size_t)r * N + n1] = pd0; }
                if (n2 < N) { att_s[(size_t)r * N + n2] = ps1; att_d[(size_t)r * N + n2] = pd1; }
            }
        }

        #pragma unroll
        for (int mt = 0; mt < 2; mt++) {
            int rr = wid * 32 + mt * 16 + t4;
            #pragma unroll
            for (int j = 0; j < 8; j++) {
                *(__half2*)&sa[rr * 72 + j * 8 + t2]       = __floats2half2_rn(c[mt][j][0], c[mt][j][1]);
                *(__half2*)&sa[(rr + 8) * 72 + j * 8 + t2] = __floats2half2_rn(c[mt][j][2], c[mt][j][3]);
            }
        }
        __syncwarp();
        #pragma unroll
        for (int it = 0; it < 8; it++) {
            int idx = it * 32 + lane;
            int rowl = idx >> 3;
            int q    = idx & 7;
            int row  = wid * 32 + rowl;
            int n = n0 + row;
            if (n < N)
                *(uint4*)&hW[((size_t)r * N + n) * 64 + q * 8] = *(uint4*)&sa[row * 72 + q * 8];
        }
        CP_WAIT0();
        __syncthreads();
    }
}

// ---------------- CSR edge aggregation (atom + reaction) ----------------
template<bool SEG>
__global__ void edge_agg_kernel(const int* __restrict__ rowptr, const uint32_t* __restrict__ epk,
                                const float* __restrict__ att_s, const float* __restrict__ att_d,
                                const __half* __restrict__ hW, const int* __restrict__ seg,
                                void* __restrict__ outh, int N, int R, int ostride, int ooff)
{
    int w = (blockIdx.x * blockDim.x + threadIdx.x) >> 5;
    int lane = threadIdx.x & 31;
    if (w >= N) return;
    int beg = rowptr[w], end = rowptr[w + 1];
    float adv = (lane < R) ? att_d[(size_t)lane * N + w] : 0.f;
    float acc0 = 0.f, acc1 = 0.f, ssum = 0.f;
    int e = beg;
    for (; e + 3 < end; e += 4) {
        uint32_t p0 = epk[e], p1 = epk[e + 1], p2 = epk[e + 2], p3 = epk[e + 3];
        int s0 = p0 & 0xFFFFF, r0 = p0 >> 20;
        int s1 = p1 & 0xFFFFF, r1 = p1 >> 20;
        int s2 = p2 & 0xFFFFF, r2 = p2 >> 20;
        int s3 = p3 & 0xFFFFF, r3 = p3 >> 20;
        float sc0 = att_s[(size_t)r0 * N + s0] + __shfl_sync(0xffffffffu, adv, r0);
        float sc1 = att_s[(size_t)r1 * N + s1] + __shfl_sync(0xffffffffu, adv, r1);
        float sc2 = att_s[(size_t)r2 * N + s2] + __shfl_sync(0xffffffffu, adv, r2);
        float sc3 = att_s[(size_t)r3 * N + s3] + __shfl_sync(0xffffffffu, adv, r3);
        sc0 = (sc0 > 0.f) ? sc0 : 0.2f * sc0;
        sc1 = (sc1 > 0.f) ? sc1 : 0.2f * sc1;
        sc2 = (sc2 > 0.f) ? sc2 : 0.2f * sc2;
        sc3 = (sc3 > 0.f) ? sc3 : 0.2f * sc3;
        float x0 = __expf(sc0), x1 = __expf(sc1), x2 = __expf(sc2), x3 = __expf(sc3);
        __half2 h0 = *(const __half2*)&hW[((size_t)r0 * N + s0) * 64 + lane * 2];
        __half2 h1 = *(const __half2*)&hW[((size_t)r1 * N + s1) * 64 + lane * 2];
        __half2 h2 = *(const __half2*)&hW[((size_t)r2 * N + s2) * 64 + lane * 2];
        __half2 h3 = *(const __half2*)&hW[((size_t)r3 * N + s3) * 64 + lane * 2];
        float2 f0 = __half22float2(h0), f1 = __half22float2(h1);
        float2 f2 = __half22float2(h2), f3 = __half22float2(h3);
        acc0 = fmaf(x0, f0.x, acc0); acc1 = fmaf(x0, f0.y, acc1);
        acc0 = fmaf(x1, f1.x, acc0); acc1 = fmaf(x1, f1.y, acc1);
        acc0 = fmaf(x2, f2.x, acc0); acc1 = fmaf(x2, f2.y, acc1);
        acc0 = fmaf(x3, f3.x, acc0); acc1 = fmaf(x3, f3.y, acc1);
        ssum += (x0 + x1) + (x2 + x3);
    }
    for (; e < end; e++) {
        uint32_t p0 = epk[e];
        int s0 = p0 & 0xFFFFF, r0 = p0 >> 20;
        float sc0 = att_s[(size_t)r0 * N + s0] + __shfl_sync(0xffffffffu, adv, r0);
        sc0 = (sc0 > 0.f) ? sc0 : 0.2f * sc0;
        float x0 = __expf(sc0);
        __half2 h0 = *(const __half2*)&hW[((size_t)r0 * N + s0) * 64 + lane * 2];
        float2 f0 = __half22float2(h0);
        acc0 = fmaf(x0, f0.x, acc0); acc1 = fmaf(x0, f0.y, acc1);
        ssum += x0;
    }
    float inv = 1.f / (ssum + 1e-9f);
    float v0 = acc0 * inv, v1 = acc1 * inv;
    v0 = (v0 > 0.f) ? v0 : expm1f(v0);
    v1 = (v1 > 0.f) ? v1 : expm1f(v1);
    if (SEG) {
        red_add_v2((float*)outh + (size_t)seg[w] * ostride + ooff + lane * 2, make_float2(v0, v1));
    } else {
        *(__half2*)((__half*)outh + (size_t)w * 64 + lane * 2) = __floats2half2_rn(v0, v1);
    }
}

__global__ void segsum_kernel(const float* __restrict__ x, const int* __restrict__ seg,
                              float* __restrict__ out, int n, int ostride, int ooff)
{
    int t = blockIdx.x * blockDim.x + threadIdx.x;
    int i = t >> 4;
    if (i >= n) return;
    int g = (t & 15) * 4;
    int s = seg[i];
    float4 v = *(const float4*)&x[(size_t)i * 64 + g];
    red_add_v4(&out[(size_t)s * ostride + ooff + g], v);
}

// ---------------- MLP head (16 rows/block — R14 measured-good version) ----------------
__global__ void fc1_kernel(const float* __restrict__ feat, const float* __restrict__ w,
                           const float* __restrict__ b, const float* __restrict__ prelu,
                           float* __restrict__ out)
{
    const int r0 = blockIdx.x * 16;
    const int c0 = blockIdx.y * 128;
    __shared__ float fs[16][128];
    #pragma unroll
    for (int it = 0; it < 4; it++) {
        int idx4 = it * 128 + threadIdx.x;
        int row = idx4 >> 5, col = (idx4 & 31) * 4;
        *(float4*)&fs[row][col] = *(const float4*)&feat[(size_t)(r0 + row) * 128 + col];
    }
    __syncthreads();
    const int col = c0 + threadIdx.x;
    float acc[16];
    #pragma unroll
    for (int j = 0; j < 16; j++) acc[j] = 0.f;
    #pragma unroll 4
    for (int k = 0; k < 128; k++) {
        float wv = w[k * 512 + col];
        #pragma unroll
        for (int j = 0; j < 16; j++) acc[j] += fs[j][k] * wv;
    }
    float bb = b[col], p = prelu[0];
    #pragma unroll
    for (int j = 0; j < 16; j++) {
        float v = acc[j] + bb;
        out[(size_t)(r0 + j) * 512 + col] = (v > 0.f) ? v : p * v;
    }
}

__global__ void fc2_kernel(const float* __restrict__ hid, const float* __restrict__ w,
                           const float* __restrict__ b, float* __restrict__ out)
{
    const int r0 = blockIdx.x * 16;
    const int c0 = blockIdx.y * 128;
    __shared__ float hs[16][512];
    #pragma unroll
    for (int it = 0; it < 16; it++) {
        int idx4 = it * 128 + threadIdx.x;
        int row = idx4 >> 7, col = (idx4 & 127) * 4;
        *(float4*)&hs[row][col] = *(const float4*)&hid[(size_t)(r0 + row) * 512 + col];
    }
    __syncthreads();
    const int col = c0 + threadIdx.x;
    if (col >= DO) return;
    float acc[16];
    #pragma unroll
    for (int j = 0; j < 16; j++) acc[j] = 0.f;
    #pragma unroll 4
    for (int k = 0; k < 512; k++) {
        float wv = w[k * DO + col];
        #pragma unroll
        for (int j = 0; j < 16; j++) acc[j] += hs[j][k] * wv;
    }
    float bb = b[col];
    #pragma unroll
    for (int j = 0; j < 16; j++)
        out[(size_t)(r0 + j) * DO + col] = acc[j] + bb;
}

// ---------------- launch ----------------
static inline int cdiv(int a, int b) { return (a + b - 1) / b; }

extern "C" void kernel_launch(void* const* d_in, const int* in_sizes, int n_in,
                              void* d_out, int out_size)
{
    const float* node_feats = (const float*)d_in[0];
    const int*   edge_src   = (const int*)  d_in[1];
    const int*   edge_dst   = (const int*)  d_in[2];
    const int*   edge_rel   = (const int*)  d_in[3];
    const int*   node2mol   = (const int*)  d_in[4];
    const int*   rxn_src    = (const int*)  d_in[5];
    const int*   rxn_dst    = (const int*)  d_in[6];
    const int*   rxn_rel    = (const int*)  d_in[7];
    const int*   mol2rxn    = (const int*)  d_in[8];
    const float* W1    = (const float*)d_in[9];
    const float* as1   = (const float*)d_in[10];
    const float* ad1   = (const float*)d_in[11];
    const float* W2    = (const float*)d_in[12];
    const float* as2   = (const float*)d_in[13];
    const float* ad2   = (const float*)d_in[14];
    const float* Wr    = (const float*)d_in[15];
    const float* asr   = (const float*)d_in[16];
    const float* adr   = (const float*)d_in[17];
    const float* w_fc1 = (const float*)d_in[18];
    const float* b_fc1 = (const float*)d_in[19];
    const float* prelu = (const float*)d_in[20];
    const float* w_fc2 = (const float*)d_in[21];
    const float* b_fc2 = (const float*)d_in[22];
    float* out = (float*)d_out;

    __half *p_hW, *p_h1, *p_Wh;
    float *p_atts, *p_attd, *p_mol, *p_feat, *p_hid;
    int *p_deg, *p_rowptr, *p_cursor, *p_bsum, *p_boff;
    int *p_deg2, *p_rowptr2, *p_cursor2, *p_bsum2, *p_boff2;
    uint32_t *p_epk, *p_epk2;
    cudaGetSymbolAddress((void**)&p_hW,     g_hW);
    cudaGetSymbolAddress((void**)&p_h1,     g_h1);
    cudaGetSymbolAddress((void**)&p_Wh,     g_Wh);
    cudaGetSymbolAddress((void**)&p_atts,   g_atts);
    cudaGetSymbolAddress((void**)&p_attd,   g_attd);
    cudaGetSymbolAddress((void**)&p_deg,    g_deg);
    cudaGetSymbolAddress((void**)&p_rowptr, g_rowptr);
    cudaGetSymbolAddress((void**)&p_cursor, g_cursor);
    cudaGetSymbolAddress((void**)&p_bsum,   g_bsum);
    cudaGetSymbolAddress((void**)&p_boff,   g_boff);
    cudaGetSymbolAddress((void**)&p_epk,    g_epk);
    cudaGetSymbolAddress((void**)&p_deg2,   g_deg2);
    cudaGetSymbolAddress((void**)&p_rowptr2,g_rowptr2);
    cudaGetSymbolAddress((void**)&p_cursor2,g_cursor2);
    cudaGetSymbolAddress((void**)&p_bsum2,  g_bsum2);
    cudaGetSymbolAddress((void**)&p_boff2,  g_boff2);
    cudaGetSymbolAddress((void**)&p_epk2,   g_epk2);
    cudaGetSymbolAddress((void**)&p_mol,    g_mol);
    cudaGetSymbolAddress((void**)&p_feat,   g_feat);
    cudaGetSymbolAddress((void**)&p_hid,    g_hid);

    const int TB = 256;
    const int NBLK  = cdiv(NN, 1024);   // 98
    const int NBLK2 = cdiv(NM, 1024);   // 5
    const int WH_N = (2 * RM + RR) * 4096;

    // ===== pre-convert weights (main stream) =====
    prep_wh_kernel<<<cdiv(WH_N, TB), TB>>>(W1, W2, Wr, p_Wh);

    // ===== fork side stream =====
    cudaStream_t s2;
    cudaStreamCreateWithFlags(&s2, cudaStreamNonBlocking);
    cudaEvent_t ev_fork, ev_join, ev_join2, ev_mol, ev_seg;
    cudaEventCreateWithFlags(&ev_fork,  cudaEventDisableTiming);
    cudaEventCreateWithFlags(&ev_join,  cudaEventDisableTiming);
    cudaEventCreateWithFlags(&ev_join2, cudaEventDisableTiming);
    cudaEventCreateWithFlags(&ev_mol,   cudaEventDisableTiming);
    cudaEventCreateWithFlags(&ev_seg,   cudaEventDisableTiming);

    cudaEventRecord(ev_fork, 0);
    cudaStreamWaitEvent(s2, ev_fork, 0);

    // --- side: atom CSR + fills ---
    filli_kernel<<<cdiv(NN, TB), TB, 0, s2>>>(p_deg, 0, NN);
    hist_kernel<<<cdiv(NE, TB), TB, 0, s2>>>(edge_dst, p_deg, NE);
    scan_bsum_kernel<<<NBLK, 256, 0, s2>>>(p_deg, p_bsum, NN);
    scan_sums_kernel<<<1, 128, 0, s2>>>(p_bsum, p_boff, NBLK);
    scan_final_kernel<<<NBLK, 256, 0, s2>>>(p_deg, p_boff, p_rowptr, p_cursor, NN, NBLK);
    scatter_kernel<<<cdiv(NE, TB), TB, 0, s2>>>(edge_src, edge_dst, edge_rel, p_cursor, p_epk, NE);
    fill_all_kernel<<<cdiv(NB * 32 > NM * 16 ? NB * 32 : NM * 16, TB), TB, 0, s2>>>(
        (float4*)p_mol, (float4*)p_feat);
    cudaEventRecord(ev_join, s2);

    // --- side (continues): reaction CSR ---
    filli_kernel<<<cdiv(NM, TB), TB, 0, s2>>>(p_deg2, 0, NM);
    hist_kernel<<<cdiv(NRE, TB), TB, 0, s2>>>(rxn_dst, p_deg2, NRE);
    scan_bsum_kernel<<<NBLK2, 256, 0, s2>>>(p_deg2, p_bsum2, NM);
    scan_sums_kernel<<<1, 128, 0, s2>>>(p_bsum2, p_boff2, NBLK2);
    scan_final_kernel<<<NBLK2, 256, 0, s2>>>(p_deg2, p_boff2, p_rowptr2, p_cursor2, NM, NBLK2);
    scatter_kernel<<<cdiv(NRE, TB), TB, 0, s2>>>(rxn_src, rxn_dst, rxn_rel, p_cursor2, p_epk2, NRE);
    cudaEventRecord(ev_join2, s2);

    // --- main: atom layer 1 ---
    hw_mma_kernel<float><<<cdiv(NN, 128), 128>>>(node_feats, p_Wh, as1, ad1,
                                                 p_hW, p_atts, p_attd, NN, RM);
    cudaStreamWaitEvent(0, ev_join, 0);
    edge_agg_kernel<false><<<cdiv(NN * 32, TB), TB>>>(p_rowptr, p_epk, p_atts, p_attd, p_hW,
                                                      (const int*)0, p_h1, NN, RM, 0, 0);

    // ===== atom layer 2 (reduces straight into mol) =====
    hw_mma_kernel<__half><<<cdiv(NN, 128), 128>>>(p_h1, p_Wh + (size_t)RM * 4096, as2, ad2,
                                                  p_hW, p_atts, p_attd, NN, RM);
    edge_agg_kernel<true><<<cdiv(NN * 32, TB), TB>>>(p_rowptr, p_epk, p_atts, p_attd, p_hW,
                                                     node2mol, p_mol, NN, RM, 64, 0);
    cudaEventRecord(ev_mol, 0);

    // --- side: direct mol sums into feat[:,64:] overlapping reaction GEMM ---
    cudaStreamWaitEvent(s2, ev_mol, 0);
    segsum_kernel<<<cdiv(NM * 16, TB), TB, 0, s2>>>(p_mol, mol2rxn, p_feat, NM, 128, 64);
    cudaEventRecord(ev_seg, s2);

    // ===== reaction-level RGAT (CSR path, straight into feat[:, :64]) =====
    hw_mma_kernel<float><<<cdiv(NM, 128), 128>>>(p_mol, p_Wh + (size_t)2 * RM * 4096, asr, adr,
                                                 p_hW, p_atts, p_attd, NM, RR);
    cudaStreamWaitEvent(0, ev_join2, 0);
    edge_agg_kernel<true><<<cdiv(NM * 32, TB), TB>>>(p_rowptr2, p_epk2, p_atts, p_attd, p_hW,
                                                     mol2rxn, p_feat, NM, RR, 128, 0);
    cudaStreamWaitEvent(0, ev_seg, 0);

    // ===== MLP head =====
    fc1_kernel<<<dim3(NB / 16, 4), 128>>>(p_feat, w_fc1, b_fc1, prelu, p_hid);
    fc2_kernel<<<dim3(NB / 16, 6), 128>>>(p_hid, w_fc2, b_fc2, out);

    cudaEventDestroy(ev_fork);
    cudaEventDestroy(ev_join);
    cudaEventDestroy(ev_join2);
    cudaEventDestroy(ev_mol);
    cudaEventDestroy(ev_seg);
    cudaStreamDestroy(s2);
}